// round 8
// baseline (speedup 1.0000x reference)
#include <cuda_runtime.h>
#include <cstddef>

#define TB 64
#define TT 1024
#define TI 64
#define TH 512
#define TR 8
#define TO 64

typedef unsigned long long ull;

// combined drive d = 0.05*noise + 0.2*(u@W_in^T + b_in), layout [T,B,H]
__device__ float g_drv[(size_t)TT * TB * TH];
// x-tilde AFTER step t (no-rec scan): g_xt[(t*B + b)*H + h]
__device__ float g_xt[(size_t)TT * TB * TH];
// 16 dots at state BEFORE step t: g_c1[(t*B+b)*16 + d]; d<8: r@M, d>=8: r@N
__device__ float g_c1[(size_t)TT * TB * 16];
// scanned products, indexed by output row m=b*T+t: g_q[m*8 + j]
__device__ float g_q[(size_t)TB * TT * 8];

__device__ __forceinline__ float fast_tanh(float x) {
    float y;
    asm("tanh.approx.f32 %0, %1;" : "=f"(y) : "f"(x));
    return y;
}
__device__ __forceinline__ float acc_tanh(float x) {
    float e;
    asm("ex2.approx.f32 %0, %1;" : "=f"(e) : "f"(x * 2.8853900817779268f));
    float d;
    asm("rcp.approx.f32 %0, %1;" : "=f"(d) : "f"(e + 1.0f));
    return fmaf(-2.0f, d, 1.0f);
}
__device__ __forceinline__ void fma2(ull& acc, ull a, ull b) {
    asm("fma.rn.f32x2 %0, %1, %2, %0;" : "+l"(acc) : "l"(a), "l"(b));
}
__device__ __forceinline__ ull dup2(float a) {
    ull d;
    asm("mov.b64 %0, {%1, %1};" : "=l"(d) : "f"(a));
    return d;
}
__device__ __forceinline__ void unpack2(ull v, float& lo, float& hi) {
    asm("mov.b64 {%0, %1}, %2;" : "=f"(lo), "=f"(hi) : "l"(v));
}

// ---------------------------------------------------------------------------
// K1: g_drv[(t*B+b)*H+h] = 0.05*noise + 0.2*(b_in[h] + u[b,t,:]·W_in[h,:])
// Launched 3x with t0 offset (instrumentation split; same total work).
// ---------------------------------------------------------------------------
__global__ void __launch_bounds__(256) k_inp(const float* __restrict__ u,
                                             const float* __restrict__ W_in,
                                             const float* __restrict__ b_in,
                                             const float* __restrict__ noise,
                                             int tofs)
{
    __shared__ __align__(16) float as[64 * 64];
    __shared__ __align__(16) float bs[64 * 64];
    const int t   = blockIdx.x + tofs;
    const int bn  = blockIdx.y;
    const int tid = threadIdx.x;

#pragma unroll
    for (int s = 0; s < 16; s++) {
        int i = tid + s * 256;
        int r = i >> 6;
        int k = i & 63;
        int sw = (k & 15) << 2;
        as[k * 64 + (r ^ sw)] = u[((size_t)((r << 10) + t)) * 64 + k];
        bs[k * 64 + (r ^ sw)] = W_in[(size_t)(bn * 64 + r) * 64 + k];
    }
    __syncthreads();

    const int tx = tid & 15;
    const int ty = tid >> 4;
    ull acc[4][2];
#pragma unroll
    for (int i = 0; i < 4; i++) { acc[i][0] = 0ull; acc[i][1] = 0ull; }

#pragma unroll
    for (int k = 0; k < 64; k++) {
        int sw = (k & 15) << 2;
        float4 a = *(const float4*)&as[k * 64 + ((ty * 4) ^ sw)];
        ulonglong2 w2 = *(const ulonglong2*)&bs[k * 64 + ((tx * 4) ^ sw)];
        ull d0 = dup2(a.x), d1 = dup2(a.y), d2 = dup2(a.z), d3 = dup2(a.w);
        fma2(acc[0][0], d0, w2.x); fma2(acc[0][1], d0, w2.y);
        fma2(acc[1][0], d1, w2.x); fma2(acc[1][1], d1, w2.y);
        fma2(acc[2][0], d2, w2.x); fma2(acc[2][1], d2, w2.y);
        fma2(acc[3][0], d3, w2.x); fma2(acc[3][1], d3, w2.y);
    }

    const int h0 = bn * 64 + tx * 4;
    float4 bias = *(const float4*)&b_in[h0];
#pragma unroll
    for (int i = 0; i < 4; i++) {
        int m = (t << 6) + ty * 4 + i;
        float v0, v1, v2, v3;
        unpack2(acc[i][0], v0, v1);
        unpack2(acc[i][1], v2, v3);
        float4 noi = *(const float4*)&noise[(size_t)m * TH + h0];
        float4 o;
        o.x = fmaf(0.05f, noi.x, 0.2f * (v0 + bias.x));
        o.y = fmaf(0.05f, noi.y, 0.2f * (v1 + bias.y));
        o.z = fmaf(0.05f, noi.z, 0.2f * (v2 + bias.z));
        o.w = fmaf(0.05f, noi.w, 0.2f * (v3 + bias.w));
        *(float4*)&g_drv[(size_t)m * TH + h0] = o;
    }
}

// ---------------------------------------------------------------------------
// K2: chunked elementwise scan, float4 strands.
// grid (64 b, 16 chunks of 64 useful t, warm-in 64). 1024 blocks -> 28 warps/SM.
// ---------------------------------------------------------------------------
__global__ void __launch_bounds__(128) k_scanA(const float* __restrict__ x0)
{
    const int b     = blockIdx.x;
    const int chunk = blockIdx.y;
    const int h4    = threadIdx.x;

    const int t0 = chunk * 64;
    const int tstart = (chunk == 0) ? 0 : t0 - 64;
    const int tend = t0 + 64;

    float4 x;
    if (chunk == 0) x = *(const float4*)&x0[b * TH + 4 * h4];
    else            x = make_float4(0.f, 0.f, 0.f, 0.f);

    const size_t s4 = (size_t)TB * TH / 4;
    const float4* dp = (const float4*)g_drv + (size_t)b * (TH / 4) + h4;
    float4*       xp = (float4*)g_xt        + (size_t)b * (TH / 4) + h4;

    float4 d[8];
#pragma unroll
    for (int p = 0; p < 8; p++)
        d[p] = dp[(size_t)(tstart + p) * s4];

    for (int t = tstart; t < tend; t += 8) {
#pragma unroll
        for (int k = 0; k < 8; k++) {
            x.x = fmaf(0.8f, x.x, d[k].x);
            x.y = fmaf(0.8f, x.y, d[k].y);
            x.z = fmaf(0.8f, x.z, d[k].z);
            x.w = fmaf(0.8f, x.w, d[k].w);
            if (t + k >= t0) xp[(size_t)(t + k) * s4] = x;
            if (t + k + 8 < tend) d[k] = dp[(size_t)(t + k + 8) * s4];
        }
    }
}

// ---------------------------------------------------------------------------
// K3: c1[m,d] = sum_h tanh(state_m[h]) * C_d[h],  m = t*B+b.
// Software-pipelined, 11-shuffle reduction. Two 512-block launches.
// ---------------------------------------------------------------------------
__global__ void __launch_bounds__(256) k_rec(const float* __restrict__ x0,
                                             const float* __restrict__ Mw,
                                             const float* __restrict__ Nw,
                                             int rowbase0)
{
    const int tid     = threadIdx.x;
    const int wid     = tid >> 5;
    const int lane    = tid & 31;
    const int rowslot = wid >> 2;
    const int jg      = wid & 3;

    const float* base = (jg < 2) ? Mw : Nw;
    const int joff = (jg & 1) * 4;
    float4 cf[16];
#pragma unroll
    for (int s = 0; s < 16; s++) {
        int hh = lane + 32 * s;
        cf[s] = *(const float4*)(base + (size_t)hh * TR + joff);
    }

    const int rowbase = rowbase0 + blockIdx.x * 64;

    float pf[16];
    {
        const int m0 = rowbase + rowslot;
        const float* src = (m0 < TB) ? (x0 + (size_t)m0 * TH)
                                     : (g_xt + (size_t)(m0 - TB) * TH);
#pragma unroll
        for (int s = 0; s < 16; s++) pf[s] = src[lane + 32 * s];
    }

    for (int it = 0; it < 32; it++) {
        const int m = rowbase + it * 2 + rowslot;

        float cur[16];
#pragma unroll
        for (int s = 0; s < 16; s++) cur[s] = pf[s];

        if (it < 31) {
            const int m2 = m + 2;
            const float* src = (m2 < TB) ? (x0 + (size_t)m2 * TH)
                                         : (g_xt + (size_t)(m2 - TB) * TH);
#pragma unroll
            for (int s = 0; s < 16; s++) pf[s] = src[lane + 32 * s];
        }

        float s0 = 0.f, s1 = 0.f, s2 = 0.f, s3 = 0.f;
#pragma unroll
        for (int s = 0; s < 16; s++) {
            float r = fast_tanh(cur[s]);
            s0 = fmaf(r, cf[s].x, s0);
            s1 = fmaf(r, cf[s].y, s1);
            s2 = fmaf(r, cf[s].z, s2);
            s3 = fmaf(r, cf[s].w, s3);
        }

        s0 += __shfl_xor_sync(0xffffffffu, s0, 16);
        s1 += __shfl_xor_sync(0xffffffffu, s1, 16);
        s2 += __shfl_xor_sync(0xffffffffu, s2, 16);
        s3 += __shfl_xor_sync(0xffffffffu, s3, 16);
        s0 += __shfl_xor_sync(0xffffffffu, s0, 8);
        s1 += __shfl_xor_sync(0xffffffffu, s1, 8);
        s2 += __shfl_xor_sync(0xffffffffu, s2, 8);
        s3 += __shfl_xor_sync(0xffffffffu, s3, 8);

        const int g = lane >> 3;
        float v = s0;
        v = (g == 1) ? s1 : v;
        v = (g == 2) ? s2 : v;
        v = (g == 3) ? s3 : v;
        v += __shfl_xor_sync(0xffffffffu, v, 4);
        v += __shfl_xor_sync(0xffffffffu, v, 2);
        v += __shfl_xor_sync(0xffffffffu, v, 1);

        if ((lane & 7) == 0)
            g_c1[(size_t)m * 16 + jg * 4 + g] = v;
    }
}

// ---------------------------------------------------------------------------
// K4: exact parallel weighted scan (unchanged)
// ---------------------------------------------------------------------------
__global__ void __launch_bounds__(256) k_qscan()
{
    const int b    = blockIdx.x >> 3;
    const int j    = blockIdx.x & 7;
    const int tid  = threadIdx.x;
    const int lane = tid & 31;
    const int wid  = tid >> 5;
    __shared__ float wtot[8];

    const int t0 = tid * 4;
    float p[4];
#pragma unroll
    for (int k = 0; k < 4; k++) {
        size_t base = (size_t)((t0 + k) * TB + b) * 16 + j;
        p[k] = g_c1[base] * g_c1[base + 8];
    }

    float l0 = p[0];
    float l1 = fmaf(0.8f, l0, p[1]);
    float l2 = fmaf(0.8f, l1, p[2]);
    float l3 = fmaf(0.8f, l2, p[3]);

    const float D1 = 0.40960000f;
    float S = l3;
    float dpow = D1;
#pragma unroll
    for (int o = 1; o < 32; o <<= 1) {
        float up = __shfl_up_sync(0xffffffffu, S, o);
        if (lane >= o) S = fmaf(dpow, up, S);
        dpow *= dpow;
    }
    if (lane == 31) wtot[wid] = S;
    __syncthreads();

    const float DW = 4.0173451106474452e-13f;   // 0.8^128
    float W = 0.f, mult = 1.f;
    for (int w = wid - 1; w >= 0; w--) {
        W = fmaf(mult, wtot[w], W);
        mult *= DW;
    }

    float Sx = __shfl_up_sync(0xffffffffu, S, 1);
    if (lane == 0) Sx = 0.f;
    float wdec = 1.f, pb = D1;
    int e = lane;
#pragma unroll
    for (int i = 0; i < 5; i++) {
        if (e & 1) wdec *= pb;
        pb *= pb;
        e >>= 1;
    }
    float E = fmaf(W, wdec, Sx);

    float f = 0.8f * E;
    float* qp = g_q + ((size_t)b * TT + t0) * 8 + j;
    qp[0]  = l0 + f; f *= 0.8f;
    qp[8]  = l1 + f; f *= 0.8f;
    qp[16] = l2 + f; f *= 0.8f;
    qp[24] = l3 + f;
}

// ---------------------------------------------------------------------------
// K5: fused traj assembly + readout GEMM (unchanged)
// ---------------------------------------------------------------------------
__global__ void __launch_bounds__(256) k_out(const float* __restrict__ W_out,
                                             const float* __restrict__ b_out,
                                             const float* __restrict__ L,
                                             float* __restrict__ outp,
                                             float* __restrict__ traj,
                                             float* __restrict__ xlast)
{
    __shared__ __align__(16) float at[64 * 64];
    __shared__ __align__(16) float bs2[64 * 64];
    const int bm  = blockIdx.x;
    const int tid = threadIdx.x;
    const int tx = tid & 15;
    const int ty = tid >> 4;
    const int kq = tid & 63;
    const int sw = (kq & 15) << 2;
    const float KC = 0.2f / ((float)TH * (float)TH);

    ull acc[4][2];
#pragma unroll
    for (int i = 0; i < 4; i++) { acc[i][0] = 0ull; acc[i][1] = 0ull; }

    for (int kc = 0; kc < 8; kc++) {
        const int h = kc * 64 + kq;
        float4 L0 = *(const float4*)(L + (size_t)h * TR);
        float4 L1 = *(const float4*)(L + (size_t)h * TR + 4);
        __syncthreads();
#pragma unroll
        for (int s = 0; s < 16; s++) {
            int r = (tid >> 6) + s * 4;
            int m = bm * 64 + r;
            int t = m & (TT - 1);
            int b = m >> 10;
            float xt = g_xt[((size_t)(t * TB + b)) * TH + h];
            const float* qp = g_q + (size_t)m * 8;
            float4 q0 = *(const float4*)qp;
            float4 q1 = *(const float4*)(qp + 4);
            float e = L0.x * q0.x;
            e = fmaf(L0.y, q0.y, e);
            e = fmaf(L0.z, q0.z, e);
            e = fmaf(L0.w, q0.w, e);
            e = fmaf(L1.x, q1.x, e);
            e = fmaf(L1.y, q1.y, e);
            e = fmaf(L1.z, q1.z, e);
            e = fmaf(L1.w, q1.w, e);
            float tv = fmaf(KC, e, xt);
            traj[(size_t)m * TH + h] = tv;
            if (t == TT - 1) xlast[(size_t)b * TH + h] = tv;
            at[kq * 64 + (r ^ sw)]  = acc_tanh(tv);
            bs2[kq * 64 + (r ^ sw)] = W_out[(size_t)r * TH + h];
        }
        __syncthreads();
#pragma unroll
        for (int k = 0; k < 64; k++) {
            int swk = (k & 15) << 2;
            float4 a = *(const float4*)&at[k * 64 + ((ty * 4) ^ swk)];
            ulonglong2 w2 = *(const ulonglong2*)&bs2[k * 64 + ((tx * 4) ^ swk)];
            ull d0 = dup2(a.x), d1 = dup2(a.y), d2 = dup2(a.z), d3 = dup2(a.w);
            fma2(acc[0][0], d0, w2.x); fma2(acc[0][1], d0, w2.y);
            fma2(acc[1][0], d1, w2.x); fma2(acc[1][1], d1, w2.y);
            fma2(acc[2][0], d2, w2.x); fma2(acc[2][1], d2, w2.y);
            fma2(acc[3][0], d3, w2.x); fma2(acc[3][1], d3, w2.y);
        }
    }

    const int o0 = tx * 4;
    float4 bias = *(const float4*)&b_out[o0];
#pragma unroll
    for (int i = 0; i < 4; i++) {
        int m = bm * 64 + ty * 4 + i;
        float v0, v1, v2, v3;
        unpack2(acc[i][0], v0, v1);
        unpack2(acc[i][1], v2, v3);
        float4 o;
        o.x = v0 + bias.x; o.y = v1 + bias.y;
        o.z = v2 + bias.z; o.w = v3 + bias.w;
        *(float4*)&outp[(size_t)m * TO + o0] = o;
    }
}

// ---------------------------------------------------------------------------
// Launcher. Inputs: u, x0, noise, L, M, N, W_in, b_in, W_out, b_out.
// Output: [output | x_last | traj].
// Launch order puts k_scanA at position #4 (profiled slot).
// ---------------------------------------------------------------------------
extern "C" void kernel_launch(void* const* d_in, const int* in_sizes, int n_in,
                              void* d_out, int out_size)
{
    (void)in_sizes; (void)n_in; (void)out_size;
    const float* u     = (const float*)d_in[0];
    const float* x0    = (const float*)d_in[1];
    const float* noise = (const float*)d_in[2];
    const float* L     = (const float*)d_in[3];
    const float* Mw    = (const float*)d_in[4];
    const float* Nw    = (const float*)d_in[5];
    const float* W_in  = (const float*)d_in[6];
    const float* b_in  = (const float*)d_in[7];
    const float* W_out = (const float*)d_in[8];
    const float* b_out = (const float*)d_in[9];

    float* outp  = (float*)d_out;
    float* xlast = outp + (size_t)TB * TT * TO;
    float* traj  = xlast + (size_t)TB * TH;

    k_inp<<<dim3(342, TH / 64), 256>>>(u, W_in, b_in, noise, 0);
    k_inp<<<dim3(342, TH / 64), 256>>>(u, W_in, b_in, noise, 342);
    k_inp<<<dim3(340, TH / 64), 256>>>(u, W_in, b_in, noise, 684);
    k_scanA<<<dim3(64, 16), 128>>>(x0);
    k_rec<<<512, 256>>>(x0, Mw, Nw, 0);
    k_rec<<<512, 256>>>(x0, Mw, Nw, 32768);
    k_qscan<<<512, 256>>>();
    k_out<<<(TB * TT) / 64, 256>>>(W_out, b_out, L, outp, traj, xlast);
}

// round 9
// speedup vs baseline: 1.4836x; 1.4836x over previous
#include <cuda_runtime.h>
#include <cstddef>

#define TB 64
#define TT 1024
#define TI 64
#define TH 512
#define TR 8
#define TO 64

typedef unsigned long long ull;

// combined drive d = 0.05*noise + 0.2*(u@W_in^T + b_in), layout [T,B,H]
__device__ float g_drv[(size_t)TT * TB * TH];
// x-tilde AFTER step t (no-rec scan), layout [T,B,H]
__device__ float g_xt[(size_t)TT * TB * TH];
// 16 dots at state BEFORE step t: g_c1[(t*B+b)*16 + d]; d<8: r@M, d>=8: r@N
__device__ float g_c1[(size_t)TT * TB * 16];

__device__ __forceinline__ float fast_tanh(float x) {
    float y;
    asm("tanh.approx.f32 %0, %1;" : "=f"(y) : "f"(x));
    return y;
}
__device__ __forceinline__ float acc_tanh(float x) {
    float e;
    asm("ex2.approx.f32 %0, %1;" : "=f"(e) : "f"(x * 2.8853900817779268f));
    float d;
    asm("rcp.approx.f32 %0, %1;" : "=f"(d) : "f"(e + 1.0f));
    return fmaf(-2.0f, d, 1.0f);
}
__device__ __forceinline__ void fma2(ull& acc, ull a, ull b) {
    asm("fma.rn.f32x2 %0, %1, %2, %0;" : "+l"(acc) : "l"(a), "l"(b));
}
__device__ __forceinline__ ull dup2(float a) {
    ull d;
    asm("mov.b64 %0, {%1, %1};" : "=l"(d) : "f"(a));
    return d;
}
__device__ __forceinline__ void unpack2(ull v, float& lo, float& hi) {
    asm("mov.b64 {%0, %1}, %2;" : "=f"(lo), "=f"(hi) : "l"(v));
}

// ---------------------------------------------------------------------------
// K1: g_drv[(t*B+b)*H+h] = 0.05*noise + 0.2*(b_in[h] + u[b,t,:]·W_in[h,:])
// (R4/R6 version, single launch)
// ---------------------------------------------------------------------------
__global__ void __launch_bounds__(256) k_inp(const float* __restrict__ u,
                                             const float* __restrict__ W_in,
                                             const float* __restrict__ b_in,
                                             const float* __restrict__ noise)
{
    __shared__ __align__(16) float as[64 * 64];
    __shared__ __align__(16) float bs[64 * 64];
    const int t   = blockIdx.x;
    const int bn  = blockIdx.y;
    const int tid = threadIdx.x;

#pragma unroll
    for (int s = 0; s < 16; s++) {
        int i = tid + s * 256;
        int r = i >> 6;
        int k = i & 63;
        int sw = (k & 15) << 2;
        as[k * 64 + (r ^ sw)] = u[((size_t)((r << 10) + t)) * 64 + k];
        bs[k * 64 + (r ^ sw)] = W_in[(size_t)(bn * 64 + r) * 64 + k];
    }
    __syncthreads();

    const int tx = tid & 15;
    const int ty = tid >> 4;
    ull acc[4][2];
#pragma unroll
    for (int i = 0; i < 4; i++) { acc[i][0] = 0ull; acc[i][1] = 0ull; }

#pragma unroll
    for (int k = 0; k < 64; k++) {
        int sw = (k & 15) << 2;
        float4 a = *(const float4*)&as[k * 64 + ((ty * 4) ^ sw)];
        ulonglong2 w2 = *(const ulonglong2*)&bs[k * 64 + ((tx * 4) ^ sw)];
        ull d0 = dup2(a.x), d1 = dup2(a.y), d2 = dup2(a.z), d3 = dup2(a.w);
        fma2(acc[0][0], d0, w2.x); fma2(acc[0][1], d0, w2.y);
        fma2(acc[1][0], d1, w2.x); fma2(acc[1][1], d1, w2.y);
        fma2(acc[2][0], d2, w2.x); fma2(acc[2][1], d2, w2.y);
        fma2(acc[3][0], d3, w2.x); fma2(acc[3][1], d3, w2.y);
    }

    const int h0 = bn * 64 + tx * 4;
    float4 bias = *(const float4*)&b_in[h0];
#pragma unroll
    for (int i = 0; i < 4; i++) {
        int m = (t << 6) + ty * 4 + i;
        float v0, v1, v2, v3;
        unpack2(acc[i][0], v0, v1);
        unpack2(acc[i][1], v2, v3);
        float4 noi = *(const float4*)&noise[(size_t)m * TH + h0];
        float4 o;
        o.x = fmaf(0.05f, noi.x, 0.2f * (v0 + bias.x));
        o.y = fmaf(0.05f, noi.y, 0.2f * (v1 + bias.y));
        o.z = fmaf(0.05f, noi.z, 0.2f * (v2 + bias.z));
        o.w = fmaf(0.05f, noi.w, 0.2f * (v3 + bias.w));
        *(float4*)&g_drv[(size_t)m * TH + h0] = o;
    }
}

// ---------------------------------------------------------------------------
// K2: chunked elementwise scan, float4 strands (R8 version, measured 54us/77%BW)
// ---------------------------------------------------------------------------
__global__ void __launch_bounds__(128) k_scanA(const float* __restrict__ x0)
{
    const int b     = blockIdx.x;
    const int chunk = blockIdx.y;
    const int h4    = threadIdx.x;

    const int t0 = chunk * 64;
    const int tstart = (chunk == 0) ? 0 : t0 - 64;
    const int tend = t0 + 64;

    float4 x;
    if (chunk == 0) x = *(const float4*)&x0[b * TH + 4 * h4];
    else            x = make_float4(0.f, 0.f, 0.f, 0.f);

    const size_t s4 = (size_t)TB * TH / 4;
    const float4* dp = (const float4*)g_drv + (size_t)b * (TH / 4) + h4;
    float4*       xp = (float4*)g_xt        + (size_t)b * (TH / 4) + h4;

    float4 d[8];
#pragma unroll
    for (int p = 0; p < 8; p++)
        d[p] = dp[(size_t)(tstart + p) * s4];

    for (int t = tstart; t < tend; t += 8) {
#pragma unroll
        for (int k = 0; k < 8; k++) {
            x.x = fmaf(0.8f, x.x, d[k].x);
            x.y = fmaf(0.8f, x.y, d[k].y);
            x.z = fmaf(0.8f, x.z, d[k].z);
            x.w = fmaf(0.8f, x.w, d[k].w);
            if (t + k >= t0) xp[(size_t)(t + k) * s4] = x;
            if (t + k + 8 < tend) d[k] = dp[(size_t)(t + k + 8) * s4];
        }
    }
}

// ---------------------------------------------------------------------------
// K3: c1[m,d] = sum_h tanh(state_m[h]) * C_d[h],  m = t*B+b.
// Software-pipelined, 11-shuffle reduction, single 1024-block launch.
// ---------------------------------------------------------------------------
__global__ void __launch_bounds__(256) k_rec(const float* __restrict__ x0,
                                             const float* __restrict__ Mw,
                                             const float* __restrict__ Nw)
{
    const int tid     = threadIdx.x;
    const int wid     = tid >> 5;
    const int lane    = tid & 31;
    const int rowslot = wid >> 2;
    const int jg      = wid & 3;

    const float* base = (jg < 2) ? Mw : Nw;
    const int joff = (jg & 1) * 4;
    float4 cf[16];
#pragma unroll
    for (int s = 0; s < 16; s++) {
        int hh = lane + 32 * s;
        cf[s] = *(const float4*)(base + (size_t)hh * TR + joff);
    }

    const int rowbase = blockIdx.x * 64;

    float pf[16];
    {
        const int m0 = rowbase + rowslot;
        const float* src = (m0 < TB) ? (x0 + (size_t)m0 * TH)
                                     : (g_xt + (size_t)(m0 - TB) * TH);
#pragma unroll
        for (int s = 0; s < 16; s++) pf[s] = src[lane + 32 * s];
    }

    for (int it = 0; it < 32; it++) {
        const int m = rowbase + it * 2 + rowslot;

        float cur[16];
#pragma unroll
        for (int s = 0; s < 16; s++) cur[s] = pf[s];

        if (it < 31) {
            const int m2 = m + 2;
            const float* src = (m2 < TB) ? (x0 + (size_t)m2 * TH)
                                         : (g_xt + (size_t)(m2 - TB) * TH);
#pragma unroll
            for (int s = 0; s < 16; s++) pf[s] = src[lane + 32 * s];
        }

        float s0 = 0.f, s1 = 0.f, s2 = 0.f, s3 = 0.f;
#pragma unroll
        for (int s = 0; s < 16; s++) {
            float r = fast_tanh(cur[s]);
            s0 = fmaf(r, cf[s].x, s0);
            s1 = fmaf(r, cf[s].y, s1);
            s2 = fmaf(r, cf[s].z, s2);
            s3 = fmaf(r, cf[s].w, s3);
        }

        s0 += __shfl_xor_sync(0xffffffffu, s0, 16);
        s1 += __shfl_xor_sync(0xffffffffu, s1, 16);
        s2 += __shfl_xor_sync(0xffffffffu, s2, 16);
        s3 += __shfl_xor_sync(0xffffffffu, s3, 16);
        s0 += __shfl_xor_sync(0xffffffffu, s0, 8);
        s1 += __shfl_xor_sync(0xffffffffu, s1, 8);
        s2 += __shfl_xor_sync(0xffffffffu, s2, 8);
        s3 += __shfl_xor_sync(0xffffffffu, s3, 8);

        const int g = lane >> 3;
        float v = s0;
        v = (g == 1) ? s1 : v;
        v = (g == 2) ? s2 : v;
        v = (g == 3) ? s3 : v;
        v += __shfl_xor_sync(0xffffffffu, v, 4);
        v += __shfl_xor_sync(0xffffffffu, v, 2);
        v += __shfl_xor_sync(0xffffffffu, v, 1);

        if ((lane & 7) == 0)
            g_c1[(size_t)m * 16 + jg * 4 + g] = v;
    }
}

// ---------------------------------------------------------------------------
// K4 (NEW): streaming traj assembly with fused q-scan.
//   q_j(t) = 0.8 q_j(t-1) + c1[t,j]*c1[t,j+8]   (warp-uniform, 64-step warm-in)
//   traj[b,t,h] = x̃[t,b,h] + KC * sum_j L[h,j] q_j(t)
// grid (64 b, 16 chunks of 64 t), 128 threads (float4 over H).
// ---------------------------------------------------------------------------
__global__ void __launch_bounds__(128) k_trajA(const float* __restrict__ L,
                                               float* __restrict__ traj,
                                               float* __restrict__ xlast)
{
    const int b     = blockIdx.x;
    const int chunk = blockIdx.y;
    const int h4    = threadIdx.x;          // h = 4*h4 .. 4*h4+3
    const float KC = 0.2f / ((float)TH * (float)TH);

    // L rows for this thread's 4 h values
    float4 La[4], Lb[4];
#pragma unroll
    for (int i = 0; i < 4; i++) {
        La[i] = *(const float4*)(L + (size_t)(4 * h4 + i) * TR);
        Lb[i] = *(const float4*)(L + (size_t)(4 * h4 + i) * TR + 4);
    }

    const int t0 = chunk * 64;
    const int tstart = (chunk == 0) ? 0 : t0 - 64;

    float4 q0 = make_float4(0.f, 0.f, 0.f, 0.f);
    float4 q1 = make_float4(0.f, 0.f, 0.f, 0.f);

    // warm-in: q-scan only (c1 rows are 64B, warp-uniform loads -> L1/L2 hot)
    for (int t = tstart; t < t0; t++) {
        const float* cp = g_c1 + (size_t)(t * TB + b) * 16;
        float4 ca = *(const float4*)(cp + 0);
        float4 cb = *(const float4*)(cp + 4);
        float4 cc = *(const float4*)(cp + 8);
        float4 cd = *(const float4*)(cp + 12);
        q0.x = fmaf(0.8f, q0.x, ca.x * cc.x);
        q0.y = fmaf(0.8f, q0.y, ca.y * cc.y);
        q0.z = fmaf(0.8f, q0.z, ca.z * cc.z);
        q0.w = fmaf(0.8f, q0.w, ca.w * cc.w);
        q1.x = fmaf(0.8f, q1.x, cb.x * cd.x);
        q1.y = fmaf(0.8f, q1.y, cb.y * cd.y);
        q1.z = fmaf(0.8f, q1.z, cb.z * cd.z);
        q1.w = fmaf(0.8f, q1.w, cb.w * cd.w);
    }

    // main: stream x̃ with an 8-deep float4 ring, apply eps, write traj
    const size_t s4 = (size_t)TB * TH / 4;
    const float4* xp = (const float4*)g_xt + (size_t)b * (TH / 4) + h4;
    float4* tp = (float4*)traj + ((size_t)b * TT) * (TH / 4) + h4;

    float4 xr[8];
#pragma unroll
    for (int p = 0; p < 8; p++)
        xr[p] = xp[(size_t)(t0 + p) * s4];

    const int tend = t0 + 64;
    for (int t = t0; t < tend; t += 8) {
#pragma unroll
        for (int k = 0; k < 8; k++) {
            const int tt = t + k;
            const float* cp = g_c1 + (size_t)(tt * TB + b) * 16;
            float4 ca = *(const float4*)(cp + 0);
            float4 cb = *(const float4*)(cp + 4);
            float4 cc = *(const float4*)(cp + 8);
            float4 cd = *(const float4*)(cp + 12);
            q0.x = fmaf(0.8f, q0.x, ca.x * cc.x);
            q0.y = fmaf(0.8f, q0.y, ca.y * cc.y);
            q0.z = fmaf(0.8f, q0.z, ca.z * cc.z);
            q0.w = fmaf(0.8f, q0.w, ca.w * cc.w);
            q1.x = fmaf(0.8f, q1.x, cb.x * cd.x);
            q1.y = fmaf(0.8f, q1.y, cb.y * cd.y);
            q1.z = fmaf(0.8f, q1.z, cb.z * cd.z);
            q1.w = fmaf(0.8f, q1.w, cb.w * cd.w);

            float4 xt = xr[k];
            float4 tv;
            {
                float e0 = La[0].x * q0.x;
                e0 = fmaf(La[0].y, q0.y, e0); e0 = fmaf(La[0].z, q0.z, e0);
                e0 = fmaf(La[0].w, q0.w, e0); e0 = fmaf(Lb[0].x, q1.x, e0);
                e0 = fmaf(Lb[0].y, q1.y, e0); e0 = fmaf(Lb[0].z, q1.z, e0);
                e0 = fmaf(Lb[0].w, q1.w, e0);
                tv.x = fmaf(KC, e0, xt.x);
                float e1 = La[1].x * q0.x;
                e1 = fmaf(La[1].y, q0.y, e1); e1 = fmaf(La[1].z, q0.z, e1);
                e1 = fmaf(La[1].w, q0.w, e1); e1 = fmaf(Lb[1].x, q1.x, e1);
                e1 = fmaf(Lb[1].y, q1.y, e1); e1 = fmaf(Lb[1].z, q1.z, e1);
                e1 = fmaf(Lb[1].w, q1.w, e1);
                tv.y = fmaf(KC, e1, xt.y);
                float e2 = La[2].x * q0.x;
                e2 = fmaf(La[2].y, q0.y, e2); e2 = fmaf(La[2].z, q0.z, e2);
                e2 = fmaf(La[2].w, q0.w, e2); e2 = fmaf(Lb[2].x, q1.x, e2);
                e2 = fmaf(Lb[2].y, q1.y, e2); e2 = fmaf(Lb[2].z, q1.z, e2);
                e2 = fmaf(Lb[2].w, q1.w, e2);
                tv.z = fmaf(KC, e2, xt.z);
                float e3 = La[3].x * q0.x;
                e3 = fmaf(La[3].y, q0.y, e3); e3 = fmaf(La[3].z, q0.z, e3);
                e3 = fmaf(La[3].w, q0.w, e3); e3 = fmaf(Lb[3].x, q1.x, e3);
                e3 = fmaf(Lb[3].y, q1.y, e3); e3 = fmaf(Lb[3].w, q1.w, e3);
                e3 = fmaf(Lb[3].z, q1.z, e3);
                tv.w = fmaf(KC, e3, xt.w);
            }
            tp[(size_t)tt * (TH / 4)] = tv;
            if (tt == TT - 1)
                *((float4*)xlast + (size_t)b * (TH / 4) + h4) = tv;
            if (tt + 8 < tend) xr[k] = xp[(size_t)(tt + 8) * s4];
        }
    }
}

// ---------------------------------------------------------------------------
// K5: readout GEMM (R2 version, measured 159us).
// out[m,o] = b_out[o] + sum_h tanh(traj[m,h]) * W_out[o,h]
// ---------------------------------------------------------------------------
__global__ void __launch_bounds__(256) k_out(const float* __restrict__ traj,
                                             const float* __restrict__ W_out,
                                             const float* __restrict__ b_out,
                                             float* __restrict__ outp)
{
    __shared__ __align__(16) float at[64 * 64];
    __shared__ __align__(16) float bs2[64 * 64];
    const int bm  = blockIdx.x;
    const int tid = threadIdx.x;
    const int tx = tid & 15;
    const int ty = tid >> 4;

    ull acc[4][2];
#pragma unroll
    for (int i = 0; i < 4; i++) { acc[i][0] = 0ull; acc[i][1] = 0ull; }

    for (int kc = 0; kc < 8; kc++) {
        __syncthreads();
#pragma unroll
        for (int s = 0; s < 16; s++) {
            int i = tid + s * 256;
            int r = i >> 6;
            int k = i & 63;
            int sw = (k & 15) << 2;
            float tv = traj[((size_t)(bm * 64 + r)) * TH + kc * 64 + k];
            at[k * 64 + (r ^ sw)]  = acc_tanh(tv);
            bs2[k * 64 + (r ^ sw)] = W_out[(size_t)r * TH + kc * 64 + k];
        }
        __syncthreads();
#pragma unroll
        for (int k = 0; k < 64; k++) {
            int swk = (k & 15) << 2;
            float4 a = *(const float4*)&at[k * 64 + ((ty * 4) ^ swk)];
            ulonglong2 w2 = *(const ulonglong2*)&bs2[k * 64 + ((tx * 4) ^ swk)];
            ull d0 = dup2(a.x), d1 = dup2(a.y), d2 = dup2(a.z), d3 = dup2(a.w);
            fma2(acc[0][0], d0, w2.x); fma2(acc[0][1], d0, w2.y);
            fma2(acc[1][0], d1, w2.x); fma2(acc[1][1], d1, w2.y);
            fma2(acc[2][0], d2, w2.x); fma2(acc[2][1], d2, w2.y);
            fma2(acc[3][0], d3, w2.x); fma2(acc[3][1], d3, w2.y);
        }
    }

    const int o0 = tx * 4;
    float4 bias = *(const float4*)&b_out[o0];
#pragma unroll
    for (int i = 0; i < 4; i++) {
        int m = bm * 64 + ty * 4 + i;
        float v0, v1, v2, v3;
        unpack2(acc[i][0], v0, v1);
        unpack2(acc[i][1], v2, v3);
        float4 o;
        o.x = v0 + bias.x; o.y = v1 + bias.y;
        o.z = v2 + bias.z; o.w = v3 + bias.w;
        *(float4*)&outp[(size_t)m * TO + o0] = o;
    }
}

// ---------------------------------------------------------------------------
// Launcher. Inputs: u, x0, noise, L, M, N, W_in, b_in, W_out, b_out.
// Output: [output | x_last | traj].
// Chain: inp -> scanA -> rec -> trajA(#4, profiled) -> out.
// ---------------------------------------------------------------------------
extern "C" void kernel_launch(void* const* d_in, const int* in_sizes, int n_in,
                              void* d_out, int out_size)
{
    (void)in_sizes; (void)n_in; (void)out_size;
    const float* u     = (const float*)d_in[0];
    const float* x0    = (const float*)d_in[1];
    const float* noise = (const float*)d_in[2];
    const float* L     = (const float*)d_in[3];
    const float* Mw    = (const float*)d_in[4];
    const float* Nw    = (const float*)d_in[5];
    const float* W_in  = (const float*)d_in[6];
    const float* b_in  = (const float*)d_in[7];
    const float* W_out = (const float*)d_in[8];
    const float* b_out = (const float*)d_in[9];

    float* outp  = (float*)d_out;
    float* xlast = outp + (size_t)TB * TT * TO;
    float* traj  = xlast + (size_t)TB * TH;

    dim3 g1(TT, TH / 64);
    k_inp<<<g1, 256>>>(u, W_in, b_in, noise);
    k_scanA<<<dim3(64, 16), 128>>>(x0);
    k_rec<<<1024, 256>>>(x0, Mw, Nw);
    k_trajA<<<dim3(64, 16), 128>>>(L, traj, xlast);
    k_out<<<(TB * TT) / 64, 256>>>(traj, W_out, b_out, outp);
}

// round 10
// speedup vs baseline: 1.5677x; 1.0567x over previous
#include <cuda_runtime.h>
#include <cstddef>

#define TB 64
#define TT 1024
#define TI 64
#define TH 512
#define TR 8
#define TO 64

typedef unsigned long long ull;

// combined drive d = 0.05*noise + 0.2*(u@W_in^T + b_in), layout [T,B,H]
__device__ float g_drv[(size_t)TT * TB * TH];
// x-tilde AFTER step t (no-rec scan), layout [T,B,H]
__device__ float g_xt[(size_t)TT * TB * TH];
// 16 dots at state BEFORE step t: g_c1[(t*B+b)*16 + d]; d<8: r@M, d>=8: r@N
__device__ float g_c1[(size_t)TT * TB * 16];
// scanned products: g_q[(b*T+t)*8 + j]
__device__ float g_q[(size_t)TB * TT * 8];

__device__ __forceinline__ float fast_tanh(float x) {
    float y;
    asm("tanh.approx.f32 %0, %1;" : "=f"(y) : "f"(x));
    return y;
}
__device__ __forceinline__ float acc_tanh(float x) {
    float e;
    asm("ex2.approx.f32 %0, %1;" : "=f"(e) : "f"(x * 2.8853900817779268f));
    float d;
    asm("rcp.approx.f32 %0, %1;" : "=f"(d) : "f"(e + 1.0f));
    return fmaf(-2.0f, d, 1.0f);
}
__device__ __forceinline__ void fma2(ull& acc, ull a, ull b) {
    asm("fma.rn.f32x2 %0, %1, %2, %0;" : "+l"(acc) : "l"(a), "l"(b));
}
__device__ __forceinline__ ull dup2(float a) {
    ull d;
    asm("mov.b64 %0, {%1, %1};" : "=l"(d) : "f"(a));
    return d;
}
__device__ __forceinline__ void unpack2(ull v, float& lo, float& hi) {
    asm("mov.b64 {%0, %1}, %2;" : "=f"(lo), "=f"(hi) : "l"(v));
}

// ---------------------------------------------------------------------------
// K1: g_drv[(t*B+b)*H+h] = 0.05*noise + 0.2*(b_in[h] + u[b,t,:]·W_in[h,:])
// ---------------------------------------------------------------------------
__global__ void __launch_bounds__(256) k_inp(const float* __restrict__ u,
                                             const float* __restrict__ W_in,
                                             const float* __restrict__ b_in,
                                             const float* __restrict__ noise)
{
    __shared__ __align__(16) float as[64 * 64];
    __shared__ __align__(16) float bs[64 * 64];
    const int t   = blockIdx.x;
    const int bn  = blockIdx.y;
    const int tid = threadIdx.x;

#pragma unroll
    for (int s = 0; s < 16; s++) {
        int i = tid + s * 256;
        int r = i >> 6;
        int k = i & 63;
        int sw = (k & 15) << 2;
        as[k * 64 + (r ^ sw)] = u[((size_t)((r << 10) + t)) * 64 + k];
        bs[k * 64 + (r ^ sw)] = W_in[(size_t)(bn * 64 + r) * 64 + k];
    }
    __syncthreads();

    const int tx = tid & 15;
    const int ty = tid >> 4;
    ull acc[4][2];
#pragma unroll
    for (int i = 0; i < 4; i++) { acc[i][0] = 0ull; acc[i][1] = 0ull; }

#pragma unroll
    for (int k = 0; k < 64; k++) {
        int sw = (k & 15) << 2;
        float4 a = *(const float4*)&as[k * 64 + ((ty * 4) ^ sw)];
        ulonglong2 w2 = *(const ulonglong2*)&bs[k * 64 + ((tx * 4) ^ sw)];
        ull d0 = dup2(a.x), d1 = dup2(a.y), d2 = dup2(a.z), d3 = dup2(a.w);
        fma2(acc[0][0], d0, w2.x); fma2(acc[0][1], d0, w2.y);
        fma2(acc[1][0], d1, w2.x); fma2(acc[1][1], d1, w2.y);
        fma2(acc[2][0], d2, w2.x); fma2(acc[2][1], d2, w2.y);
        fma2(acc[3][0], d3, w2.x); fma2(acc[3][1], d3, w2.y);
    }

    const int h0 = bn * 64 + tx * 4;
    float4 bias = *(const float4*)&b_in[h0];
#pragma unroll
    for (int i = 0; i < 4; i++) {
        int m = (t << 6) + ty * 4 + i;
        float v0, v1, v2, v3;
        unpack2(acc[i][0], v0, v1);
        unpack2(acc[i][1], v2, v3);
        float4 noi = *(const float4*)&noise[(size_t)m * TH + h0];
        float4 o;
        o.x = fmaf(0.05f, noi.x, 0.2f * (v0 + bias.x));
        o.y = fmaf(0.05f, noi.y, 0.2f * (v1 + bias.y));
        o.z = fmaf(0.05f, noi.z, 0.2f * (v2 + bias.z));
        o.w = fmaf(0.05f, noi.w, 0.2f * (v3 + bias.w));
        *(float4*)&g_drv[(size_t)m * TH + h0] = o;
    }
}

// ---------------------------------------------------------------------------
// K2: chunked elementwise scan, float4 strands (measured 54us / 77% BW)
// ---------------------------------------------------------------------------
__global__ void __launch_bounds__(128) k_scanA(const float* __restrict__ x0)
{
    const int b     = blockIdx.x;
    const int chunk = blockIdx.y;
    const int h4    = threadIdx.x;

    const int t0 = chunk * 64;
    const int tstart = (chunk == 0) ? 0 : t0 - 64;
    const int tend = t0 + 64;

    float4 x;
    if (chunk == 0) x = *(const float4*)&x0[b * TH + 4 * h4];
    else            x = make_float4(0.f, 0.f, 0.f, 0.f);

    const size_t s4 = (size_t)TB * TH / 4;
    const float4* dp = (const float4*)g_drv + (size_t)b * (TH / 4) + h4;
    float4*       xp = (float4*)g_xt        + (size_t)b * (TH / 4) + h4;

    float4 d[8];
#pragma unroll
    for (int p = 0; p < 8; p++)
        d[p] = dp[(size_t)(tstart + p) * s4];

    for (int t = tstart; t < tend; t += 8) {
#pragma unroll
        for (int k = 0; k < 8; k++) {
            x.x = fmaf(0.8f, x.x, d[k].x);
            x.y = fmaf(0.8f, x.y, d[k].y);
            x.z = fmaf(0.8f, x.z, d[k].z);
            x.w = fmaf(0.8f, x.w, d[k].w);
            if (t + k >= t0) xp[(size_t)(t + k) * s4] = x;
            if (t + k + 8 < tend) d[k] = dp[(size_t)(t + k + 8) * s4];
        }
    }
}

// ---------------------------------------------------------------------------
// K3: c1[m,d] = sum_h tanh(state_m[h]) * C_d[h],  m = t*B+b. (measured ~102us)
// ---------------------------------------------------------------------------
__global__ void __launch_bounds__(256) k_rec(const float* __restrict__ x0,
                                             const float* __restrict__ Mw,
                                             const float* __restrict__ Nw)
{
    const int tid     = threadIdx.x;
    const int wid     = tid >> 5;
    const int lane    = tid & 31;
    const int rowslot = wid >> 2;
    const int jg      = wid & 3;

    const float* base = (jg < 2) ? Mw : Nw;
    const int joff = (jg & 1) * 4;
    float4 cf[16];
#pragma unroll
    for (int s = 0; s < 16; s++) {
        int hh = lane + 32 * s;
        cf[s] = *(const float4*)(base + (size_t)hh * TR + joff);
    }

    const int rowbase = blockIdx.x * 64;

    float pf[16];
    {
        const int m0 = rowbase + rowslot;
        const float* src = (m0 < TB) ? (x0 + (size_t)m0 * TH)
                                     : (g_xt + (size_t)(m0 - TB) * TH);
#pragma unroll
        for (int s = 0; s < 16; s++) pf[s] = src[lane + 32 * s];
    }

    for (int it = 0; it < 32; it++) {
        const int m = rowbase + it * 2 + rowslot;

        float cur[16];
#pragma unroll
        for (int s = 0; s < 16; s++) cur[s] = pf[s];

        if (it < 31) {
            const int m2 = m + 2;
            const float* src = (m2 < TB) ? (x0 + (size_t)m2 * TH)
                                         : (g_xt + (size_t)(m2 - TB) * TH);
#pragma unroll
            for (int s = 0; s < 16; s++) pf[s] = src[lane + 32 * s];
        }

        float s0 = 0.f, s1 = 0.f, s2 = 0.f, s3 = 0.f;
#pragma unroll
        for (int s = 0; s < 16; s++) {
            float r = fast_tanh(cur[s]);
            s0 = fmaf(r, cf[s].x, s0);
            s1 = fmaf(r, cf[s].y, s1);
            s2 = fmaf(r, cf[s].z, s2);
            s3 = fmaf(r, cf[s].w, s3);
        }

        s0 += __shfl_xor_sync(0xffffffffu, s0, 16);
        s1 += __shfl_xor_sync(0xffffffffu, s1, 16);
        s2 += __shfl_xor_sync(0xffffffffu, s2, 16);
        s3 += __shfl_xor_sync(0xffffffffu, s3, 16);
        s0 += __shfl_xor_sync(0xffffffffu, s0, 8);
        s1 += __shfl_xor_sync(0xffffffffu, s1, 8);
        s2 += __shfl_xor_sync(0xffffffffu, s2, 8);
        s3 += __shfl_xor_sync(0xffffffffu, s3, 8);

        const int g = lane >> 3;
        float v = s0;
        v = (g == 1) ? s1 : v;
        v = (g == 2) ? s2 : v;
        v = (g == 3) ? s3 : v;
        v += __shfl_xor_sync(0xffffffffu, v, 4);
        v += __shfl_xor_sync(0xffffffffu, v, 2);
        v += __shfl_xor_sync(0xffffffffu, v, 1);

        if ((lane & 7) == 0)
            g_c1[(size_t)m * 16 + jg * 4 + g] = v;
    }
}

// ---------------------------------------------------------------------------
// K4: exact parallel weighted scan  q_t = 0.8 q_{t-1} + c1[t,j]*c1[t,j+8]
// (measured 11us)
// ---------------------------------------------------------------------------
__global__ void __launch_bounds__(256) k_qscan()
{
    const int b    = blockIdx.x >> 3;
    const int j    = blockIdx.x & 7;
    const int tid  = threadIdx.x;
    const int lane = tid & 31;
    const int wid  = tid >> 5;
    __shared__ float wtot[8];

    const int t0 = tid * 4;
    float p[4];
#pragma unroll
    for (int k = 0; k < 4; k++) {
        size_t base = (size_t)((t0 + k) * TB + b) * 16 + j;
        p[k] = g_c1[base] * g_c1[base + 8];
    }

    float l0 = p[0];
    float l1 = fmaf(0.8f, l0, p[1]);
    float l2 = fmaf(0.8f, l1, p[2]);
    float l3 = fmaf(0.8f, l2, p[3]);

    const float D1 = 0.40960000f;
    float S = l3;
    float dpow = D1;
#pragma unroll
    for (int o = 1; o < 32; o <<= 1) {
        float up = __shfl_up_sync(0xffffffffu, S, o);
        if (lane >= o) S = fmaf(dpow, up, S);
        dpow *= dpow;
    }
    if (lane == 31) wtot[wid] = S;
    __syncthreads();

    const float DW = 4.0173451106474452e-13f;   // 0.8^128
    float W = 0.f, mult = 1.f;
    for (int w = wid - 1; w >= 0; w--) {
        W = fmaf(mult, wtot[w], W);
        mult *= DW;
    }

    float Sx = __shfl_up_sync(0xffffffffu, S, 1);
    if (lane == 0) Sx = 0.f;
    float wdec = 1.f, pb = D1;
    int e = lane;
#pragma unroll
    for (int i = 0; i < 5; i++) {
        if (e & 1) wdec *= pb;
        pb *= pb;
        e >>= 1;
    }
    float E = fmaf(W, wdec, Sx);

    float f = 0.8f * E;
    float* qp = g_q + ((size_t)b * TT + t0) * 8 + j;
    qp[0]  = l0 + f; f *= 0.8f;
    qp[8]  = l1 + f; f *= 0.8f;
    qp[16] = l2 + f; f *= 0.8f;
    qp[24] = l3 + f;
}

// ---------------------------------------------------------------------------
// K5: streaming traj assembly, dependency-free (q precomputed).
//   traj[b,t,h] = x̃[t,b,h] + KC * sum_j L[h,j] q[b,t,j]
// grid (64 b, 16 chunks of 64 t), 128 threads (float4 over H).
// ---------------------------------------------------------------------------
__global__ void __launch_bounds__(128) k_trajA(const float* __restrict__ L,
                                               float* __restrict__ traj,
                                               float* __restrict__ xlast)
{
    const int b     = blockIdx.x;
    const int chunk = blockIdx.y;
    const int h4    = threadIdx.x;
    const float KC = 0.2f / ((float)TH * (float)TH);

    float4 La[4], Lb[4];
#pragma unroll
    for (int i = 0; i < 4; i++) {
        La[i] = *(const float4*)(L + (size_t)(4 * h4 + i) * TR);
        Lb[i] = *(const float4*)(L + (size_t)(4 * h4 + i) * TR + 4);
    }

    const int t0 = chunk * 64;
    const int tend = t0 + 64;

    const size_t s4 = (size_t)TB * TH / 4;
    const float4* xp = (const float4*)g_xt + (size_t)b * (TH / 4) + h4;
    float4* tp = (float4*)traj + ((size_t)b * TT) * (TH / 4) + h4;
    const float* qbase = g_q + ((size_t)b * TT) * 8;

    float4 xr[8];
#pragma unroll
    for (int p = 0; p < 8; p++)
        xr[p] = xp[(size_t)(t0 + p) * s4];

    for (int t = t0; t < tend; t += 8) {
#pragma unroll
        for (int k = 0; k < 8; k++) {
            const int tt = t + k;
            float4 q0 = *(const float4*)(qbase + (size_t)tt * 8);
            float4 q1 = *(const float4*)(qbase + (size_t)tt * 8 + 4);

            float4 xt = xr[k];
            float4 tv;
            float e0 = La[0].x * q0.x;
            e0 = fmaf(La[0].y, q0.y, e0); e0 = fmaf(La[0].z, q0.z, e0);
            e0 = fmaf(La[0].w, q0.w, e0); e0 = fmaf(Lb[0].x, q1.x, e0);
            e0 = fmaf(Lb[0].y, q1.y, e0); e0 = fmaf(Lb[0].z, q1.z, e0);
            e0 = fmaf(Lb[0].w, q1.w, e0);
            tv.x = fmaf(KC, e0, xt.x);
            float e1 = La[1].x * q0.x;
            e1 = fmaf(La[1].y, q0.y, e1); e1 = fmaf(La[1].z, q0.z, e1);
            e1 = fmaf(La[1].w, q0.w, e1); e1 = fmaf(Lb[1].x, q1.x, e1);
            e1 = fmaf(Lb[1].y, q1.y, e1); e1 = fmaf(Lb[1].z, q1.z, e1);
            e1 = fmaf(Lb[1].w, q1.w, e1);
            tv.y = fmaf(KC, e1, xt.y);
            float e2 = La[2].x * q0.x;
            e2 = fmaf(La[2].y, q0.y, e2); e2 = fmaf(La[2].z, q0.z, e2);
            e2 = fmaf(La[2].w, q0.w, e2); e2 = fmaf(Lb[2].x, q1.x, e2);
            e2 = fmaf(Lb[2].y, q1.y, e2); e2 = fmaf(Lb[2].z, q1.z, e2);
            e2 = fmaf(Lb[2].w, q1.w, e2);
            tv.z = fmaf(KC, e2, xt.z);
            float e3 = La[3].x * q0.x;
            e3 = fmaf(La[3].y, q0.y, e3); e3 = fmaf(La[3].z, q0.z, e3);
            e3 = fmaf(La[3].w, q0.w, e3); e3 = fmaf(Lb[3].x, q1.x, e3);
            e3 = fmaf(Lb[3].y, q1.y, e3); e3 = fmaf(Lb[3].z, q1.z, e3);
            e3 = fmaf(Lb[3].w, q1.w, e3);
            tv.w = fmaf(KC, e3, xt.w);

            tp[(size_t)tt * (TH / 4)] = tv;
            if (tt == TT - 1)
                *((float4*)xlast + (size_t)b * (TH / 4) + h4) = tv;
            if (tt + 8 < tend) xr[k] = xp[(size_t)(tt + 8) * s4];
        }
    }
}

// ---------------------------------------------------------------------------
// K6: readout GEMM, 128-row tiles, 8x4 outputs per thread.
// out[m,o] = b_out[o] + sum_h tanh(traj[m,h]) * W_out[o,h]
// ---------------------------------------------------------------------------
__global__ void __launch_bounds__(256) k_out(const float* __restrict__ traj,
                                             const float* __restrict__ W_out,
                                             const float* __restrict__ b_out,
                                             float* __restrict__ outp)
{
    __shared__ __align__(16) float at[64 * 128];   // [k][r]  32KB
    __shared__ __align__(16) float bs2[64 * 64];   // [k][o]  16KB
    const int bm  = blockIdx.x;                    // 512 blocks, 128 rows each
    const int tid = threadIdx.x;
    const int tx = tid & 15;        // o sub-block (4 outputs)
    const int ty = tid >> 4;        // row sub-block (8 rows)

    ull acc[8][2];
#pragma unroll
    for (int i = 0; i < 8; i++) { acc[i][0] = 0ull; acc[i][1] = 0ull; }

    for (int kc = 0; kc < 8; kc++) {
        __syncthreads();
        // fill at: 128 rows x 64 k
#pragma unroll
        for (int s = 0; s < 32; s++) {
            int i = tid + s * 256;
            int r = i >> 6;           // 0..127
            int k = i & 63;
            int sw = (k & 15) << 2;
            float tv = traj[((size_t)(bm * 128 + r)) * TH + kc * 64 + k];
            at[k * 128 + (r ^ sw)] = acc_tanh(tv);
        }
        // fill bs2: 64 o x 64 k
#pragma unroll
        for (int s = 0; s < 16; s++) {
            int i = tid + s * 256;
            int r = i >> 6;           // 0..63
            int k = i & 63;
            int sw = (k & 15) << 2;
            bs2[k * 64 + (r ^ sw)] = W_out[(size_t)r * TH + kc * 64 + k];
        }
        __syncthreads();
#pragma unroll
        for (int k = 0; k < 64; k++) {
            int swk = (k & 15) << 2;
            float4 a0 = *(const float4*)&at[k * 128 + ((ty * 8) ^ swk)];
            float4 a1 = *(const float4*)&at[k * 128 + (((ty * 8) ^ swk) ^ 4)];
            ulonglong2 w2 = *(const ulonglong2*)&bs2[k * 64 + ((tx * 4) ^ swk)];
            ull d0 = dup2(a0.x), d1 = dup2(a0.y), d2 = dup2(a0.z), d3 = dup2(a0.w);
            ull d4 = dup2(a1.x), d5 = dup2(a1.y), d6 = dup2(a1.z), d7 = dup2(a1.w);
            fma2(acc[0][0], d0, w2.x); fma2(acc[0][1], d0, w2.y);
            fma2(acc[1][0], d1, w2.x); fma2(acc[1][1], d1, w2.y);
            fma2(acc[2][0], d2, w2.x); fma2(acc[2][1], d2, w2.y);
            fma2(acc[3][0], d3, w2.x); fma2(acc[3][1], d3, w2.y);
            fma2(acc[4][0], d4, w2.x); fma2(acc[4][1], d4, w2.y);
            fma2(acc[5][0], d5, w2.x); fma2(acc[5][1], d5, w2.y);
            fma2(acc[6][0], d6, w2.x); fma2(acc[6][1], d6, w2.y);
            fma2(acc[7][0], d7, w2.x); fma2(acc[7][1], d7, w2.y);
        }
    }

    const int o0 = tx * 4;
    float4 bias = *(const float4*)&b_out[o0];
#pragma unroll
    for (int i = 0; i < 8; i++) {
        // acc[i] corresponds to row (ty*8) with bit2 possibly swapped by ^4:
        // a0 held rows (ty*8)^0..3 region, a1 rows ((ty*8)^4)..: both map
        // back to plain indices because the ^swk in loads cancels with the
        // fill-side r^sw. Row for acc slot i is ty*8 + i.
        int m = bm * 128 + ty * 8 + i;
        float v0, v1, v2, v3;
        unpack2(acc[i][0], v0, v1);
        unpack2(acc[i][1], v2, v3);
        float4 o;
        o.x = v0 + bias.x; o.y = v1 + bias.y;
        o.z = v2 + bias.z; o.w = v3 + bias.w;
        *(float4*)&outp[(size_t)m * TO + o0] = o;
    }
}

// ---------------------------------------------------------------------------
// Launcher. Inputs: u, x0, noise, L, M, N, W_in, b_in, W_out, b_out.
// Output: [output | x_last | traj].
// Chain: inp -> scanA -> rec -> qscan(#4, profiled) -> trajA -> out.
// ---------------------------------------------------------------------------
extern "C" void kernel_launch(void* const* d_in, const int* in_sizes, int n_in,
                              void* d_out, int out_size)
{
    (void)in_sizes; (void)n_in; (void)out_size;
    const float* u     = (const float*)d_in[0];
    const float* x0    = (const float*)d_in[1];
    const float* noise = (const float*)d_in[2];
    const float* L     = (const float*)d_in[3];
    const float* Mw    = (const float*)d_in[4];
    const float* Nw    = (const float*)d_in[5];
    const float* W_in  = (const float*)d_in[6];
    const float* b_in  = (const float*)d_in[7];
    const float* W_out = (const float*)d_in[8];
    const float* b_out = (const float*)d_in[9];

    float* outp  = (float*)d_out;
    float* xlast = outp + (size_t)TB * TT * TO;
    float* traj  = xlast + (size_t)TB * TH;

    dim3 g1(TT, TH / 64);
    k_inp<<<g1, 256>>>(u, W_in, b_in, noise);
    k_scanA<<<dim3(64, 16), 128>>>(x0);
    k_rec<<<1024, 256>>>(x0, Mw, Nw);
    k_qscan<<<512, 256>>>();
    k_trajA<<<dim3(64, 16), 128>>>(L, traj, xlast);
    k_out<<<(TB * TT) / 128, 256>>>(traj, W_out, b_out, outp);
}